// round 2
// baseline (speedup 1.0000x reference)
#include <cuda_runtime.h>
#include <math.h>

// Reference reduces to: x0 = exp(-50*((X-.5)^2+(Y-.5)^2)); 100x { x = 0.25*Mask1*(N+S+E+W) }
// (down-sweep / coarse solve / up-sweep are dead code w.r.t. the returned value)

#define H 1024
#define NT 100
#define TSTEPS 5
#define NKER (NT / TSTEPS)            // 20
#define TILE_W 128
#define TILE_H 64
#define HALO TSTEPS                   // 5
#define EXW (TILE_W + 2 * HALO)       // 138
#define EXH (TILE_H + 2 * HALO)       // 74
#define PITCH 140
#define SMEM_FLOATS (EXH * PITCH)     // 10360
#define SMEM_BYTES (3 * SMEM_FLOATS * 4)  // 124320 B

__device__ float g_buf0[H * H];
__device__ float g_buf1[H * H];

__global__ void init_kernel(const float* __restrict__ X, const float* __restrict__ Y,
                            float* __restrict__ out) {
    int i = blockIdx.x * blockDim.x + threadIdx.x;
    float dx = X[i] - 0.5f;
    float dy = Y[i] - 0.5f;
    out[i] = expf(-50.0f * (dx * dx + dy * dy));
}

// One CTA = one 128x64 output tile. Loads halo-extended (74x138) region + premultiplied
// mask into smem, runs TSTEPS Jacobi steps smem-resident, stores interior.
//
// Validity: after step s, cells at distance >= s from the extended-tile edge are
// exact. After TSTEPS=5 steps the valid region is rows/cols [5, EX-6], which is
// exactly the stored interior. Out-of-domain cells have ms==0 so they stay exactly
// 0 (zero-padding semantics) every step.
__global__ void __launch_bounds__(512, 1)
jacobi_block(const float* __restrict__ in, const float* __restrict__ mask,
             float* __restrict__ out) {
    extern __shared__ float smem[];
    float* xs0 = smem;
    float* xs1 = smem + SMEM_FLOATS;
    float* ms  = smem + 2 * SMEM_FLOATS;

    const int r0 = blockIdx.y * TILE_H - HALO;
    const int c0 = blockIdx.x * TILE_W - HALO;
    const int tx = threadIdx.x;   // 0..31
    const int ty = threadIdx.y;   // 0..15
    const int tid = ty * 32 + tx;

    // Load extended tile + premultiplied mask (0.25*mask; 0 when out of domain).
    for (int i = tid; i < EXH * EXW; i += 512) {
        int r = i / EXW;
        int c = i - r * EXW;
        int gr = r0 + r;
        int gc = c0 + c;
        bool ok = ((unsigned)gr < (unsigned)H) && ((unsigned)gc < (unsigned)H);
        int o = r * PITCH + c;
        xs0[o] = ok ? in[gr * H + gc] : 0.0f;
        ms[o]  = ok ? 0.25f * mask[gr * H + gc] : 0.0f;
    }
    __syncthreads();

    float* cur = xs0;
    float* nxt = xs1;
    #pragma unroll
    for (int s = 0; s < TSTEPS; s++) {
        #pragma unroll
        for (int i = 0; i < 5; i++) {
            int r = 1 + ty + i * 16;
            if (r < EXH - 1) {
                #pragma unroll
                for (int j = 0; j < 5; j++) {
                    int c = 1 + tx + j * 32;
                    if (c < EXW - 1) {
                        int o = r * PITCH + c;
                        float v = (cur[o - PITCH] + cur[o + PITCH]) +
                                  (cur[o - 1] + cur[o + 1]);
                        nxt[o] = ms[o] * v;
                    }
                }
            }
        }
        float* t = cur; cur = nxt; nxt = t;
        __syncthreads();
    }

    // Store the valid interior (cur holds step-TSTEPS values).
    #pragma unroll
    for (int i = 0; i < TILE_H / 16; i++) {
        int r = HALO + ty + i * 16;
        #pragma unroll
        for (int j = 0; j < TILE_W / 32; j++) {
            int c = HALO + tx + j * 32;
            out[(r0 + r) * H + (c0 + c)] = cur[r * PITCH + c];
        }
    }
}

extern "C" void kernel_launch(void* const* d_in, const int* in_sizes, int n_in,
                              void* d_out, int out_size) {
    (void)in_sizes; (void)n_in; (void)out_size;
    const float* X  = (const float*)d_in[0];
    const float* Y  = (const float*)d_in[1];
    const float* M1 = (const float*)d_in[2];   // Mask1: [1,1,1024,1024]
    float* out = (float*)d_out;

    float* b0 = nullptr;
    float* b1 = nullptr;
    cudaGetSymbolAddress((void**)&b0, g_buf0);
    cudaGetSymbolAddress((void**)&b1, g_buf1);

    cudaFuncSetAttribute(jacobi_block, cudaFuncAttributeMaxDynamicSharedMemorySize,
                         SMEM_BYTES);

    init_kernel<<<(H * H) / 256, 256>>>(X, Y, b0);

    dim3 grid(H / TILE_W, H / TILE_H);   // (8, 16) = 128 CTAs
    dim3 block(32, 16);                  // 512 threads

    float* bufs[2] = { b0, b1 };
    int cur = 0;
    for (int k = 0; k < NKER; k++) {
        float* o = (k == NKER - 1) ? out : bufs[cur ^ 1];
        jacobi_block<<<grid, block, SMEM_BYTES>>>(bufs[cur], M1, o);
        cur ^= 1;
    }
}

// round 3
// speedup vs baseline: 1.4045x; 1.4045x over previous
#include <cuda_runtime.h>
#include <math.h>

// Reference reduces to: x0 = exp(-50*((X-.5)^2+(Y-.5)^2)); 100x { x = 0.25*Mask1*(N+S+E+W) }
// (down-sweep / coarse solve / up-sweep are dead code w.r.t. the returned value)

#define H 1024
#define NT 100
#define TSTEPS 5
#define NKER (NT / TSTEPS)            // 20
#define TILE_W 128
#define TILE_H 32
#define HALO TSTEPS                   // 5
#define EXW (TILE_W + 2 * HALO)       // 138 (we pad to PITCH=140 and compute full width)
#define EXH (TILE_H + 2 * HALO)       // 42
#define PITCH 140                     // 35 float4 groups exactly
#define NGROUPS ((EXH - 2) * (PITCH / 4))   // 40*35 = 1400 vector groups per step
#define SMEM_FLOATS (EXH * PITCH)     // 5880
#define SMEM_BYTES (3 * SMEM_FLOATS * 4)    // 70560 B -> 2 CTAs/SM

__device__ float g_buf0[H * H];
__device__ float g_buf1[H * H];

__global__ void init_kernel(const float* __restrict__ X, const float* __restrict__ Y,
                            float* __restrict__ out) {
    int i = blockIdx.x * blockDim.x + threadIdx.x;
    float dx = X[i] - 0.5f;
    float dy = Y[i] - 0.5f;
    out[i] = expf(-50.0f * (dx * dx + dy * dy));
}

// One CTA = 128x32 output tile, halo 5, 5 smem-resident Jacobi steps, float4 compute.
//
// Validity: needed region at step s is rows/cols [s, EX-s). We compute rows [1,EXH-1)
// at FULL padded width (cols 0..139, edge groups wrap-read the neighboring row);
// the resulting garbage propagates inward 1 cell/step and provably never enters the
// needed cone (final interior = rows/cols [HALO, HALO+TILE)). Out-of-domain cells
// carry ms==0 and stay exactly 0, matching zero padding.
__global__ void __launch_bounds__(512, 2)
jacobi_block(const float* __restrict__ in, const float* __restrict__ mask,
             float* __restrict__ out) {
    extern __shared__ float smem[];
    float* xs0 = smem;
    float* xs1 = smem + SMEM_FLOATS;
    float* ms  = smem + 2 * SMEM_FLOATS;

    const int r0 = blockIdx.y * TILE_H - HALO;
    const int c0 = blockIdx.x * TILE_W - HALO;
    const int tid = threadIdx.x;          // 0..511

    // Load extended tile + premultiplied mask (0.25*mask; 0 outside domain).
    // Fill the full padded buffer so no uninitialized smem is ever read.
    for (int i = tid; i < SMEM_FLOATS; i += 512) {
        int r = i / PITCH;
        int c = i - r * PITCH;
        int gr = r0 + r;
        int gc = c0 + c;
        bool ok = ((unsigned)gr < (unsigned)H) && ((unsigned)gc < (unsigned)H);
        xs0[i] = ok ? in[gr * H + gc] : 0.0f;
        ms[i]  = ok ? 0.25f * mask[gr * H + gc] : 0.0f;
    }
    __syncthreads();

    float* cur = xs0;
    float* nxt = xs1;
    #pragma unroll
    for (int s = 0; s < TSTEPS; s++) {
        #pragma unroll
        for (int k = 0; k < 3; k++) {
            int g = tid + k * 512;
            if (k < 2 || g < NGROUPS) {
                int o = PITCH + 4 * g;     // rows 1..EXH-2, contiguous groups
                float4 u = *(const float4*)(cur + o - PITCH);
                float4 d = *(const float4*)(cur + o + PITCH);
                float4 c = *(const float4*)(cur + o);
                float  l = cur[o - 1];
                float  r = cur[o + 4];
                float4 m = *(const float4*)(ms + o);
                float4 v;
                v.x = m.x * ((u.x + d.x) + (l   + c.y));
                v.y = m.y * ((u.y + d.y) + (c.x + c.z));
                v.z = m.z * ((u.z + d.z) + (c.y + c.w));
                v.w = m.w * ((u.w + d.w) + (c.z + r));
                *(float4*)(nxt + o) = v;
            }
        }
        float* t = cur; cur = nxt; nxt = t;
        __syncthreads();
    }

    // Store the valid interior: rows/cols [HALO, HALO+TILE).
    #pragma unroll
    for (int k = 0; k < (TILE_H * TILE_W) / 512; k++) {   // 8 iterations
        int idx = tid + k * 512;
        int r = HALO + (idx >> 7);          // /128
        int c = HALO + (idx & 127);
        out[(r0 + r) * H + (c0 + c)] = cur[r * PITCH + c];
    }
}

extern "C" void kernel_launch(void* const* d_in, const int* in_sizes, int n_in,
                              void* d_out, int out_size) {
    (void)in_sizes; (void)n_in; (void)out_size;
    const float* X  = (const float*)d_in[0];
    const float* Y  = (const float*)d_in[1];
    const float* M1 = (const float*)d_in[2];   // Mask1: [1,1,1024,1024]
    float* out = (float*)d_out;

    float* b0 = nullptr;
    float* b1 = nullptr;
    cudaGetSymbolAddress((void**)&b0, g_buf0);
    cudaGetSymbolAddress((void**)&b1, g_buf1);

    cudaFuncSetAttribute(jacobi_block, cudaFuncAttributeMaxDynamicSharedMemorySize,
                         SMEM_BYTES);

    init_kernel<<<(H * H) / 256, 256>>>(X, Y, b0);

    dim3 grid(H / TILE_W, H / TILE_H);   // (8, 32) = 256 CTAs
    dim3 block(512);

    float* bufs[2] = { b0, b1 };
    int cur = 0;
    for (int k = 0; k < NKER; k++) {
        float* o = (k == NKER - 1) ? out : bufs[cur ^ 1];
        jacobi_block<<<grid, block, SMEM_BYTES>>>(bufs[cur], M1, o);
        cur ^= 1;
    }
}

// round 4
// speedup vs baseline: 1.7878x; 1.2729x over previous
#include <cuda_runtime.h>
#include <math.h>

// Reference reduces to: x0 = exp(-50*((X-.5)^2+(Y-.5)^2)); 100x { x = 0.25*Mask1*(N+S+E+W) }
// (down-sweep / coarse solve / up-sweep are dead code w.r.t. the returned value)

#define H 1024
#define NT 100
#define TSTEPS 10
#define NKER (NT / TSTEPS)              // 10
#define TILE_W 128
#define TILE_H 32
#define HALO TSTEPS                     // 10
#define EXW (TILE_W + 2 * HALO)         // 148
#define EXH (TILE_H + 2 * HALO)         // 52
#define PITCH 148                       // == EXW, 37 float4-groups per row exactly
#define GPR 37                          // groups per row
#define NGROUPS (EXH * GPR)             // 1924 (all rows)
#define SMEM_FLOATS (EXH * PITCH)       // 7696
#define SMEM_BYTES (2 * SMEM_FLOATS * 4)  // 61568 B -> 2 CTAs/SM

__device__ float g_buf0[H * H];
__device__ float g_buf1[H * H];

__global__ void init_kernel(const float* __restrict__ X, const float* __restrict__ Y,
                            float* __restrict__ out) {
    int i = blockIdx.x * blockDim.x + threadIdx.x;
    float dx = X[i] - 0.5f;
    float dy = Y[i] - 0.5f;
    out[i] = expf(-50.0f * (dx * dx + dy * dy));
}

// One CTA = 128x32 output tile, halo 10, 10 smem-resident Jacobi steps.
// Mask (premultiplied 0.25, zero outside domain) and each thread's center values
// live in REGISTERS; smem holds only cur/nxt ping-pong buffers.
//
// Validity: padded width == EXW == PITCH, so every smem cell is real (or
// zero-outside-domain) data. Column wrap at group edges (o-1 / o+4 crossing a row)
// injects error that travels 1 col/step inward: after 10 steps it reaches cols
// 9 and 138; the needed interior is cols [10,138) -> untouched. Row cone: step s
// computes rows [s, EXH-s); row r at step s reads rows r+-1 valid at step s-1.
// Final interior rows [HALO, HALO+TILE_H) == [10,42) == step-10 compute range.
__global__ void __launch_bounds__(512, 2)
jacobi_block(const float* __restrict__ in, const float* __restrict__ mask,
             float* __restrict__ out) {
    extern __shared__ float smem[];
    float* xs0 = smem;
    float* xs1 = smem + SMEM_FLOATS;

    const int r0 = blockIdx.y * TILE_H - HALO;
    const int c0 = blockIdx.x * TILE_W - HALO;
    const int tid = threadIdx.x;            // 0..511

    // Fill cur buffer (zero outside domain).
    for (int i = tid; i < SMEM_FLOATS; i += 512) {
        int r = i / PITCH;
        int c = i - r * PITCH;
        int gr = r0 + r;
        int gc = c0 + c;
        bool ok = ((unsigned)gr < (unsigned)H) && ((unsigned)gc < (unsigned)H);
        xs0[i] = ok ? in[gr * H + gc] : 0.0f;
    }

    // Per-thread group set: g = tid + 512*k, k=0..3 (covers all 1924 groups).
    // Load premultiplied mask into registers (element-wise, bounds-checked).
    float4 mreg[4];
    #pragma unroll
    for (int k = 0; k < 4; k++) {
        int g = tid + 512 * k;
        float4 m = make_float4(0.f, 0.f, 0.f, 0.f);
        if (g < NGROUPS) {
            int r = g / GPR;
            int cbase = 4 * (g - r * GPR);
            int gr = r0 + r;
            if ((unsigned)gr < (unsigned)H) {
                const float* mrow = mask + gr * H;
                int gc = c0 + cbase;
                if ((unsigned)gc     < (unsigned)H) m.x = 0.25f * mrow[gc];
                if ((unsigned)(gc+1) < (unsigned)H) m.y = 0.25f * mrow[gc+1];
                if ((unsigned)(gc+2) < (unsigned)H) m.z = 0.25f * mrow[gc+2];
                if ((unsigned)(gc+3) < (unsigned)H) m.w = 0.25f * mrow[gc+3];
            }
        }
        mreg[k] = m;
    }
    __syncthreads();

    // Load initial center values into registers.
    float4 creg[4];
    #pragma unroll
    for (int k = 0; k < 4; k++) {
        int g = tid + 512 * k;
        creg[k] = (g < NGROUPS) ? *(const float4*)(xs0 + 4 * g)
                                : make_float4(0.f, 0.f, 0.f, 0.f);
    }

    float* cur = xs0;
    float* nxt = xs1;
    #pragma unroll
    for (int s = 1; s <= TSTEPS; s++) {
        const int glo = s * GPR;              // first group of row s
        const int ghi = (EXH - s) * GPR;      // one past last group of row EXH-1-s
        #pragma unroll
        for (int k = 0; k < 4; k++) {
            int g = tid + 512 * k;
            if (g >= glo && g < ghi) {
                int o = 4 * g;
                float4 u = *(const float4*)(cur + o - PITCH);
                float4 d = *(const float4*)(cur + o + PITCH);
                float  l = cur[o - 1];
                float  rr = cur[o + 4];
                float4 c = creg[k];
                float4 m = mreg[k];
                float4 v;
                v.x = m.x * ((u.x + d.x) + (l   + c.y));
                v.y = m.y * ((u.y + d.y) + (c.x + c.z));
                v.z = m.z * ((u.z + d.z) + (c.y + c.w));
                v.w = m.w * ((u.w + d.w) + (c.z + rr));
                creg[k] = v;
                *(float4*)(nxt + o) = v;
            }
        }
        float* t = cur; cur = nxt; nxt = t;
        __syncthreads();
    }

    // Store the valid interior: rows/cols [HALO, HALO+TILE).
    #pragma unroll
    for (int k = 0; k < (TILE_H * TILE_W) / 512; k++) {   // 8 iterations
        int idx = tid + k * 512;
        int r = HALO + (idx >> 7);            // /128
        int c = HALO + (idx & 127);
        out[(r0 + r) * H + (c0 + c)] = cur[r * PITCH + c];
    }
}

extern "C" void kernel_launch(void* const* d_in, const int* in_sizes, int n_in,
                              void* d_out, int out_size) {
    (void)in_sizes; (void)n_in; (void)out_size;
    const float* X  = (const float*)d_in[0];
    const float* Y  = (const float*)d_in[1];
    const float* M1 = (const float*)d_in[2];   // Mask1: [1,1,1024,1024]
    float* out = (float*)d_out;

    float* b0 = nullptr;
    float* b1 = nullptr;
    cudaGetSymbolAddress((void**)&b0, g_buf0);
    cudaGetSymbolAddress((void**)&b1, g_buf1);

    cudaFuncSetAttribute(jacobi_block, cudaFuncAttributeMaxDynamicSharedMemorySize,
                         SMEM_BYTES);

    init_kernel<<<(H * H) / 256, 256>>>(X, Y, b0);

    dim3 grid(H / TILE_W, H / TILE_H);   // (8, 32) = 256 CTAs
    dim3 block(512);

    float* bufs[2] = { b0, b1 };
    int cur = 0;
    for (int k = 0; k < NKER; k++) {
        float* o = (k == NKER - 1) ? out : bufs[cur ^ 1];
        jacobi_block<<<grid, block, SMEM_BYTES>>>(bufs[cur], M1, o);
        cur ^= 1;
    }
}

// round 5
// speedup vs baseline: 1.9186x; 1.0732x over previous
#include <cuda_runtime.h>
#include <math.h>

// Reference reduces to: x0 = exp(-50*((X-.5)^2+(Y-.5)^2)); 100x { x = 0.25*Mask1*(N+S+E+W) }
// (down-sweep / coarse solve / up-sweep are dead code w.r.t. the returned value)

#define H 1024
#define NT 100
#define TSTEPS 10
#define NKER (NT / TSTEPS)              // 10
#define TILE_W 128
#define TILE_H 32
#define HALO TSTEPS                     // 10
#define EXW (TILE_W + 2 * HALO)         // 148
#define EXH (TILE_H + 2 * HALO)         // 52
#define PITCH 148                       // == EXW, 37 float4-groups per row
#define GPR 37
#define NSTACKS ((EXH / 4) * GPR)       // 13 row-bands * 37 = 481
#define SMEM_FLOATS (EXH * PITCH)       // 7696
#define SMEM_BYTES (2 * SMEM_FLOATS * 4)  // 61568 B -> 2 CTAs/SM

__device__ float g_buf0[H * H];
__device__ float g_buf1[H * H];

__global__ void init_kernel(const float* __restrict__ X, const float* __restrict__ Y,
                            float* __restrict__ out) {
    int i = blockIdx.x * blockDim.x + threadIdx.x;
    float dx = X[i] - 0.5f;
    float dy = Y[i] - 0.5f;
    out[i] = expf(-50.0f * (dx * dx + dy * dy));
}

// One CTA = 128x32 tile, halo 10, 10 smem-resident steps.
// Each thread owns a 4-row x 4-col register stack (center values + premultiplied
// mask). Vertical in-stack neighbors from registers; stack-top/bottom rows via
// 2 LDS.128; horizontal neighbors via lane+-1 shuffles (warp edges: scalar LDS).
//
// Validity: row cone [s, EXH-s) is exact. Horizontal wrap/shuffle garbage enters
// only cols 0 and 147 each step, spreading 1 col/step: after 10 steps it covers
// cols <=9 and >=138; needed interior cols are [10,138) -> untouched. Rows read
// by in-cone cells were in the (wider) cone on the previous step, so register
// and smem staleness outside the cone is never observed.
__global__ void __launch_bounds__(512, 2)
jacobi_block(const float* __restrict__ in, const float* __restrict__ mask,
             float* __restrict__ out) {
    extern __shared__ float smem[];
    float* xs0 = smem;
    float* xs1 = smem + SMEM_FLOATS;

    const int r0b = blockIdx.y * TILE_H - HALO;
    const int c0  = blockIdx.x * TILE_W - HALO;
    const int tid = threadIdx.x;            // 0..511
    const int lane = tid & 31;

    // Fill cur buffer (zero outside domain).
    for (int i = tid; i < SMEM_FLOATS; i += 512) {
        int r = i / PITCH;
        int c = i - r * PITCH;
        int gr = r0b + r;
        int gc = c0 + c;
        bool ok = ((unsigned)gr < (unsigned)H) && ((unsigned)gc < (unsigned)H);
        xs0[i] = ok ? in[gr * H + gc] : 0.0f;
    }

    const bool act = tid < NSTACKS;
    int band = tid / GPR;
    int cg   = tid - band * GPR;
    if (!act) { band = (EXH / 4) - 1; cg = GPR - 1; }   // clamp: valid addrs, no stores
    const int r0 = band * 4;                 // stack top row
    const int o0 = r0 * PITCH + 4 * cg;

    // Premultiplied mask into registers (element-wise, bounds-checked).
    float4 m[4];
    #pragma unroll
    for (int i = 0; i < 4; i++) {
        float4 mm = make_float4(0.f, 0.f, 0.f, 0.f);
        int gr = r0b + r0 + i;
        if (act && (unsigned)gr < (unsigned)H) {
            const float* mrow = mask + gr * H;
            int gc = c0 + 4 * cg;
            if ((unsigned)gc       < (unsigned)H) mm.x = 0.25f * mrow[gc];
            if ((unsigned)(gc + 1) < (unsigned)H) mm.y = 0.25f * mrow[gc + 1];
            if ((unsigned)(gc + 2) < (unsigned)H) mm.z = 0.25f * mrow[gc + 2];
            if ((unsigned)(gc + 3) < (unsigned)H) mm.w = 0.25f * mrow[gc + 3];
        }
        m[i] = mm;
    }
    __syncthreads();

    // Initial center values into registers.
    float4 c4[4];
    #pragma unroll
    for (int i = 0; i < 4; i++)
        c4[i] = *(const float4*)(xs0 + o0 + i * PITCH);

    float* cur = xs0;
    float* nxt = xs1;
    #pragma unroll
    for (int s = 1; s <= TSTEPS; s++) {
        bool rc[4];
        #pragma unroll
        for (int i = 0; i < 4; i++) {
            int r = r0 + i;
            rc[i] = act && (r >= s) && (r < EXH - s);
        }
        float4 u4 = rc[0] ? *(const float4*)(cur + o0 - PITCH)
                          : make_float4(0.f, 0.f, 0.f, 0.f);
        float4 d4 = rc[3] ? *(const float4*)(cur + o0 + 4 * PITCH)
                          : make_float4(0.f, 0.f, 0.f, 0.f);

        float4 below_old = u4;   // step-(s-1) value of the row below row i
        #pragma unroll
        for (int i = 0; i < 4; i++) {
            float l  = __shfl_up_sync(0xffffffffu, c4[i].w, 1);
            float rr = __shfl_down_sync(0xffffffffu, c4[i].x, 1);
            int oi = o0 + i * PITCH;
            if (lane == 0  && rc[i]) l  = cur[oi - 1];
            if (lane == 31 && rc[i]) rr = cur[oi + 4];
            float4 dn = (i == 3) ? d4 : c4[i + 1];
            float4 cc = c4[i];
            float4 v;
            v.x = m[i].x * ((below_old.x + dn.x) + (l    + cc.y));
            v.y = m[i].y * ((below_old.y + dn.y) + (cc.x + cc.z));
            v.z = m[i].z * ((below_old.z + dn.z) + (cc.y + cc.w));
            v.w = m[i].w * ((below_old.w + dn.w) + (cc.z + rr));
            below_old = cc;
            if (rc[i]) {
                c4[i] = v;
                *(float4*)(nxt + oi) = v;
            }
        }
        float* t = cur; cur = nxt; nxt = t;
        __syncthreads();
    }

    // Store the valid interior: rows/cols [HALO, HALO+TILE).
    #pragma unroll
    for (int k = 0; k < (TILE_H * TILE_W) / 512; k++) {   // 8 iterations
        int idx = tid + k * 512;
        int r = HALO + (idx >> 7);            // /128
        int c = HALO + (idx & 127);
        out[(r0b + r) * H + (c0 + c)] = cur[r * PITCH + c];
    }
}

extern "C" void kernel_launch(void* const* d_in, const int* in_sizes, int n_in,
                              void* d_out, int out_size) {
    (void)in_sizes; (void)n_in; (void)out_size;
    const float* X  = (const float*)d_in[0];
    const float* Y  = (const float*)d_in[1];
    const float* M1 = (const float*)d_in[2];   // Mask1: [1,1,1024,1024]
    float* out = (float*)d_out;

    float* b0 = nullptr;
    float* b1 = nullptr;
    cudaGetSymbolAddress((void**)&b0, g_buf0);
    cudaGetSymbolAddress((void**)&b1, g_buf1);

    cudaFuncSetAttribute(jacobi_block, cudaFuncAttributeMaxDynamicSharedMemorySize,
                         SMEM_BYTES);

    init_kernel<<<(H * H) / 256, 256>>>(X, Y, b0);

    dim3 grid(H / TILE_W, H / TILE_H);   // (8, 32) = 256 CTAs
    dim3 block(512);

    float* bufs[2] = { b0, b1 };
    int cur = 0;
    for (int k = 0; k < NKER; k++) {
        float* o = (k == NKER - 1) ? out : bufs[cur ^ 1];
        jacobi_block<<<grid, block, SMEM_BYTES>>>(bufs[cur], M1, o);
        cur ^= 1;
    }
}

// round 6
// speedup vs baseline: 2.0399x; 1.0632x over previous
#include <cuda_runtime.h>
#include <math.h>

// Reference reduces to: x0 = exp(-50*((X-.5)^2+(Y-.5)^2)); 100x { x = 0.25*Mask1*(N+S+E+W) }
// (down-sweep / coarse solve / up-sweep are dead code w.r.t. the returned value)

#define H 1024
#define NT 100
#define TSTEPS 10
#define NKER (NT / TSTEPS)              // 10
#define TILE_W 128
#define TILE_H 64
#define HALO TSTEPS                     // 10
#define EXW (TILE_W + 2 * HALO)         // 148
#define EXH (TILE_H + 2 * HALO)         // 84
#define PITCH 148                       // == EXW, 37 float4-groups per row
#define GPR 37
#define NBANDS (EXH / 4)                // 21
#define NSTACKS (NBANDS * GPR)          // 777
#define NTHREADS 1024
#define SMEM_FLOATS (EXH * PITCH)       // 12432
#define SMEM_BYTES (2 * SMEM_FLOATS * 4)  // 99456 B -> 1 CTA/SM

typedef unsigned long long u64;

__device__ float g_buf0[H * H];
__device__ float g_buf1[H * H];

__device__ __forceinline__ u64 addx2(u64 a, u64 b) {
    u64 r; asm("add.rn.f32x2 %0,%1,%2;" : "=l"(r) : "l"(a), "l"(b)); return r;
}
__device__ __forceinline__ u64 mulx2(u64 a, u64 b) {
    u64 r; asm("mul.rn.f32x2 %0,%1,%2;" : "=l"(r) : "l"(a), "l"(b)); return r;
}
__device__ __forceinline__ u64 pk(float lo, float hi) {
    u64 r; asm("mov.b64 %0,{%1,%2};" : "=l"(r) : "f"(lo), "f"(hi)); return r;
}
__device__ __forceinline__ void unpk(u64 a, float& lo, float& hi) {
    asm("mov.b64 {%0,%1},%2;" : "=f"(lo), "=f"(hi) : "l"(a));
}

__global__ void init_kernel(const float* __restrict__ X, const float* __restrict__ Y,
                            float* __restrict__ out) {
    int i = blockIdx.x * blockDim.x + threadIdx.x;
    float dx = X[i] - 0.5f;
    float dy = Y[i] - 0.5f;
    out[i] = expf(-50.0f * (dx * dx + dy * dy));
}

// One CTA (1024 threads, 1/SM) = 128x64 output tile, halo 10, 10 smem steps.
// Each active thread owns a 4-row x 4-col stack; center + premultiplied mask live
// in registers as packed f32x2 pairs; arithmetic uses add/mul.rn.f32x2.
//
// Validity: row cone [s, EXH-s) exact; final interior rows [10,74). Horizontal
// wrap/shuffle/band-edge garbage enters only cols 0 and 147 and spreads 1 col/step:
// after 10 steps it covers cols <=9 and >=138; interior cols [10,138) untouched.
__global__ void __launch_bounds__(NTHREADS, 1)
jacobi_block(const float* __restrict__ in, const float* __restrict__ mask,
             float* __restrict__ out) {
    extern __shared__ float smem[];
    float* xs0 = smem;
    float* xs1 = smem + SMEM_FLOATS;

    const int r0b = blockIdx.y * TILE_H - HALO;
    const int c0  = blockIdx.x * TILE_W - HALO;
    const int tid = threadIdx.x;            // 0..1023
    const int lane = tid & 31;

    // Fill cur buffer (zero outside domain).
    for (int i = tid; i < SMEM_FLOATS; i += NTHREADS) {
        int r = i / PITCH;
        int c = i - r * PITCH;
        int gr = r0b + r;
        int gc = c0 + c;
        bool ok = ((unsigned)gr < (unsigned)H) && ((unsigned)gc < (unsigned)H);
        xs0[i] = ok ? in[gr * H + gc] : 0.0f;
    }

    const bool act = tid < NSTACKS;
    int band = tid / GPR;
    int cg   = tid - band * GPR;
    if (!act) { band = NBANDS - 1; cg = GPR - 1; }   // clamp: valid addrs, no stores
    const int r0 = band * 4;                 // stack top row
    const int o0 = r0 * PITCH + 4 * cg;

    // Premultiplied mask into packed registers (bounds-checked, zero outside).
    u64 m01[4], m23[4];
    #pragma unroll
    for (int i = 0; i < 4; i++) {
        float a = 0.f, b = 0.f, c = 0.f, d = 0.f;
        int gr = r0b + r0 + i;
        if (act && (unsigned)gr < (unsigned)H) {
            const float* mrow = mask + gr * H;
            int gc = c0 + 4 * cg;
            if ((unsigned)gc       < (unsigned)H) a = 0.25f * mrow[gc];
            if ((unsigned)(gc + 1) < (unsigned)H) b = 0.25f * mrow[gc + 1];
            if ((unsigned)(gc + 2) < (unsigned)H) c = 0.25f * mrow[gc + 2];
            if ((unsigned)(gc + 3) < (unsigned)H) d = 0.25f * mrow[gc + 3];
        }
        m01[i] = pk(a, b);
        m23[i] = pk(c, d);
    }
    __syncthreads();

    // Initial center values into packed registers.
    u64 c01[4], c23[4];
    #pragma unroll
    for (int i = 0; i < 4; i++) {
        ulonglong2 v = *(const ulonglong2*)(xs0 + o0 + i * PITCH);
        c01[i] = v.x;
        c23[i] = v.y;
    }

    float* cur = xs0;
    float* nxt = xs1;
    #pragma unroll
    for (int s = 1; s <= TSTEPS; s++) {
        bool rc[4];
        #pragma unroll
        for (int i = 0; i < 4; i++) {
            int r = r0 + i;
            rc[i] = act && (r >= s) && (r < EXH - s);
        }
        ulonglong2 uu = rc[0] ? *(const ulonglong2*)(cur + o0 - PITCH)
                              : make_ulonglong2(0ull, 0ull);
        ulonglong2 dd = rc[3] ? *(const ulonglong2*)(cur + o0 + 4 * PITCH)
                              : make_ulonglong2(0ull, 0ull);

        u64 b01 = uu.x, b23 = uu.y;   // step-(s-1) values of the row above row i
        #pragma unroll
        for (int i = 0; i < 4; i++) {
            float cx, cy, cz, cw;
            unpk(c01[i], cx, cy);
            unpk(c23[i], cz, cw);
            float l  = __shfl_up_sync(0xffffffffu, cw, 1);
            float rr = __shfl_down_sync(0xffffffffu, cx, 1);
            int oi = o0 + i * PITCH;
            if (lane == 0  && rc[i]) l  = cur[oi - 1];
            if (lane == 31 && rc[i]) rr = cur[oi + 4];
            u64 dn01, dn23;
            if (i == 3) { dn01 = dd.x; dn23 = dd.y; }
            else        { dn01 = c01[i + 1]; dn23 = c23[i + 1]; }
            u64 mid = pk(cy, cz);
            u64 h01 = addx2(pk(l, cx), mid);
            u64 h23 = addx2(mid, pk(cw, rr));
            u64 v01 = mulx2(addx2(addx2(b01, dn01), h01), m01[i]);
            u64 v23 = mulx2(addx2(addx2(b23, dn23), h23), m23[i]);
            b01 = c01[i];
            b23 = c23[i];
            if (rc[i]) {
                c01[i] = v01;
                c23[i] = v23;
                *(ulonglong2*)(nxt + oi) = make_ulonglong2(v01, v23);
            }
        }
        float* t = cur; cur = nxt; nxt = t;
        __syncthreads();
    }

    // Store the valid interior: rows/cols [HALO, HALO+TILE). (10 swaps -> cur==xs0)
    #pragma unroll
    for (int k = 0; k < (TILE_H * TILE_W) / NTHREADS; k++) {   // 8 iterations
        int idx = tid + k * NTHREADS;
        int r = HALO + (idx >> 7);            // /128
        int c = HALO + (idx & 127);
        out[(r0b + r) * H + (c0 + c)] = cur[r * PITCH + c];
    }
}

extern "C" void kernel_launch(void* const* d_in, const int* in_sizes, int n_in,
                              void* d_out, int out_size) {
    (void)in_sizes; (void)n_in; (void)out_size;
    const float* X  = (const float*)d_in[0];
    const float* Y  = (const float*)d_in[1];
    const float* M1 = (const float*)d_in[2];   // Mask1: [1,1,1024,1024]
    float* out = (float*)d_out;

    float* b0 = nullptr;
    float* b1 = nullptr;
    cudaGetSymbolAddress((void**)&b0, g_buf0);
    cudaGetSymbolAddress((void**)&b1, g_buf1);

    cudaFuncSetAttribute(jacobi_block, cudaFuncAttributeMaxDynamicSharedMemorySize,
                         SMEM_BYTES);

    init_kernel<<<(H * H) / 256, 256>>>(X, Y, b0);

    dim3 grid(H / TILE_W, H / TILE_H);   // (8, 16) = 128 CTAs
    dim3 block(NTHREADS);

    float* bufs[2] = { b0, b1 };
    int cur = 0;
    for (int k = 0; k < NKER; k++) {
        float* o = (k == NKER - 1) ? out : bufs[cur ^ 1];
        jacobi_block<<<grid, block, SMEM_BYTES>>>(bufs[cur], M1, o);
        cur ^= 1;
    }
}

// round 7
// speedup vs baseline: 2.2042x; 1.0806x over previous
#include <cuda_runtime.h>
#include <math.h>

// Reference reduces to: x0 = exp(-50*((X-.5)^2+(Y-.5)^2)); 100x { x = 0.25*Mask1*(N+S+E+W) }
// (down-sweep / coarse solve / up-sweep are dead code w.r.t. the returned value)
//
// Persistent-kernel version: 128 CTAs (1/SM, single wave), 10 super-steps of 10
// smem-resident Jacobi steps each; halo-ring exchange through ping-pong global
// buffers with an epoch-based grid barrier (replay-safe, no reset needed).

#define H 1024
#define NT 100
#define TSTEPS 10
#define NSS (NT / TSTEPS)               // 10 super-steps
#define TILE_W 128
#define TILE_H 64
#define HALO TSTEPS                     // 10
#define EXW (TILE_W + 2 * HALO)         // 148
#define EXH (TILE_H + 2 * HALO)         // 84
#define PITCH 148
#define GPR 37
#define NBANDS (EXH / 4)                // 21
#define NSTACKS (NBANDS * GPR)          // 777
#define NTHREADS 1024
#define GRID_X (H / TILE_W)             // 8
#define GRID_Y (H / TILE_H)             // 16
#define NCTA (GRID_X * GRID_Y)          // 128
#define SMEM_FLOATS (EXH * PITCH)       // 12432
#define SMEM_BYTES (2 * SMEM_FLOATS * 4)  // 99456 B -> 1 CTA/SM

typedef unsigned long long u64;

__device__ float g_buf0[H * H];
__device__ float g_buf1[H * H];
__device__ volatile unsigned g_arr[NCTA];   // zero-init; epochs, monotone across replays
__device__ volatile unsigned g_go;

__device__ __forceinline__ u64 addx2(u64 a, u64 b) {
    u64 r; asm("add.rn.f32x2 %0,%1,%2;" : "=l"(r) : "l"(a), "l"(b)); return r;
}
__device__ __forceinline__ u64 mulx2(u64 a, u64 b) {
    u64 r; asm("mul.rn.f32x2 %0,%1,%2;" : "=l"(r) : "l"(a), "l"(b)); return r;
}
__device__ __forceinline__ u64 pk(float lo, float hi) {
    u64 r; asm("mov.b64 %0,{%1,%2};" : "=l"(r) : "f"(lo), "f"(hi)); return r;
}
__device__ __forceinline__ void unpk(u64 a, float& lo, float& hi) {
    asm("mov.b64 {%0,%1},%2;" : "=f"(lo), "=f"(hi) : "l"(a));
}

// Epoch grid barrier. All 128 CTAs are co-resident (1/SM, regs force 1 CTA/SM,
// grid < SM count). Epochs only increase; replay-safe without resets.
__device__ __forceinline__ void grid_barrier(int bid, unsigned ep) {
    __syncthreads();                         // all CTA threads' prior work done
    if (threadIdx.x == 0) {
        __threadfence();                     // publish this CTA's global writes
        g_arr[bid] = ep;
    }
    if (bid == 0) {
        if (threadIdx.x < NCTA) {
            while (g_arr[threadIdx.x] < ep) __nanosleep(32);
        }
        __syncthreads();
        if (threadIdx.x == 0) { __threadfence(); g_go = ep; }
    }
    if (threadIdx.x == 0) {
        while (g_go < ep) __nanosleep(32);
        __threadfence();                     // acquire
    }
    __syncthreads();
}

__global__ void __launch_bounds__(NTHREADS, 1)
jacobi_persist(const float* __restrict__ X, const float* __restrict__ Y,
               const float* __restrict__ mask, float* __restrict__ out) {
    extern __shared__ float smem[];
    float* xs0 = smem;
    float* xs1 = smem + SMEM_FLOATS;

    const int bx = blockIdx.x, by = blockIdx.y;
    const int bid = by * GRID_X + bx;
    const int r0b = by * TILE_H - HALO;
    const int c0  = bx * TILE_W - HALO;
    const int tid = threadIdx.x;
    const int lane = tid & 31;

    // Epoch base: all entries equal at launch start (previous launch synced).
    const unsigned ep0 = g_arr[0];

    // Initial fill: x0 = exp(-50*((X-.5)^2+(Y-.5)^2)), zero outside domain.
    for (int i = tid; i < SMEM_FLOATS; i += NTHREADS) {
        int r = i / PITCH;
        int c = i - r * PITCH;
        int gr = r0b + r;
        int gc = c0 + c;
        float v = 0.f;
        if ((unsigned)gr < (unsigned)H && (unsigned)gc < (unsigned)H) {
            int g = gr * H + gc;
            float dx = X[g] - 0.5f;
            float dy = Y[g] - 0.5f;
            v = expf(-50.0f * (dx * dx + dy * dy));
        }
        xs0[i] = v;
    }

    const bool act = tid < NSTACKS;
    int band = tid / GPR;
    int cg   = tid - band * GPR;
    if (!act) { band = NBANDS - 1; cg = GPR - 1; }   // clamp: valid addrs, no stores
    const int r0 = band * 4;
    const int o0 = r0 * PITCH + 4 * cg;

    // Premultiplied mask into packed registers (bounds-checked, zero outside).
    u64 m01[4], m23[4];
    #pragma unroll
    for (int i = 0; i < 4; i++) {
        float a = 0.f, b = 0.f, c = 0.f, d = 0.f;
        int gr = r0b + r0 + i;
        if (act && (unsigned)gr < (unsigned)H) {
            const float* mrow = mask + gr * H;
            int gc = c0 + 4 * cg;
            if ((unsigned)gc       < (unsigned)H) a = 0.25f * mrow[gc];
            if ((unsigned)(gc + 1) < (unsigned)H) b = 0.25f * mrow[gc + 1];
            if ((unsigned)(gc + 2) < (unsigned)H) c = 0.25f * mrow[gc + 2];
            if ((unsigned)(gc + 3) < (unsigned)H) d = 0.25f * mrow[gc + 3];
        }
        m01[i] = pk(a, b);
        m23[i] = pk(c, d);
    }
    __syncthreads();

    // Center values into packed registers.
    u64 c01[4], c23[4];
    #pragma unroll
    for (int i = 0; i < 4; i++) {
        ulonglong2 v = *(const ulonglong2*)(xs0 + o0 + i * PITCH);
        c01[i] = v.x;
        c23[i] = v.y;
    }

    #pragma unroll 1
    for (int ss = 0; ss < NSS; ss++) {
        // ---- 10 smem-resident Jacobi steps (cone-predicated; ends with cur==xs0) ----
        float* cur = xs0;
        float* nxt = xs1;
        #pragma unroll
        for (int s = 1; s <= TSTEPS; s++) {
            bool rc[4];
            #pragma unroll
            for (int i = 0; i < 4; i++) {
                int r = r0 + i;
                rc[i] = act && (r >= s) && (r < EXH - s);
            }
            ulonglong2 uu = rc[0] ? *(const ulonglong2*)(cur + o0 - PITCH)
                                  : make_ulonglong2(0ull, 0ull);
            ulonglong2 dd = rc[3] ? *(const ulonglong2*)(cur + o0 + 4 * PITCH)
                                  : make_ulonglong2(0ull, 0ull);

            u64 b01 = uu.x, b23 = uu.y;
            #pragma unroll
            for (int i = 0; i < 4; i++) {
                float cx, cy, cz, cw;
                unpk(c01[i], cx, cy);
                unpk(c23[i], cz, cw);
                float l  = __shfl_up_sync(0xffffffffu, cw, 1);
                float rr = __shfl_down_sync(0xffffffffu, cx, 1);
                int oi = o0 + i * PITCH;
                if (lane == 0  && rc[i]) l  = cur[oi - 1];
                if (lane == 31 && rc[i]) rr = cur[oi + 4];
                u64 dn01, dn23;
                if (i == 3) { dn01 = dd.x; dn23 = dd.y; }
                else        { dn01 = c01[i + 1]; dn23 = c23[i + 1]; }
                u64 mid = pk(cy, cz);
                u64 h01 = addx2(pk(l, cx), mid);
                u64 h23 = addx2(mid, pk(cw, rr));
                u64 v01 = mulx2(addx2(addx2(b01, dn01), h01), m01[i]);
                u64 v23 = mulx2(addx2(addx2(b23, dn23), h23), m23[i]);
                b01 = c01[i];
                b23 = c23[i];
                if (rc[i]) {
                    c01[i] = v01;
                    c23[i] = v23;
                    *(ulonglong2*)(nxt + oi) = make_ulonglong2(v01, v23);
                }
            }
            float* t = cur; cur = nxt; nxt = t;
            __syncthreads();
        }

        // ---- write interior (rows/cols [HALO, HALO+TILE)) from xs0 ----
        float* wb = (ss == NSS - 1) ? out : ((ss & 1) ? g_buf1 : g_buf0);
        #pragma unroll
        for (int k = 0; k < (TILE_H * TILE_W) / NTHREADS; k++) {   // 8 iterations
            int idx = tid + k * NTHREADS;
            int r = HALO + (idx >> 7);
            int c = HALO + (idx & 127);
            wb[(r0b + r) * H + (c0 + c)] = xs0[r * PITCH + c];
        }
        if (ss == NSS - 1) break;

        grid_barrier(bid, ep0 + (unsigned)ss + 1u);

        // ---- refresh halo ring of xs0 from this super-step's buffer ----
        const float* rb = (ss & 1) ? g_buf1 : g_buf0;
        // top + bottom row bands: rows [0,HALO) and [HALO+TILE_H, EXH), all cols
        for (int i = tid; i < 2 * HALO * EXW; i += NTHREADS) {
            int r = i / EXW;
            int c = i - (i / EXW) * EXW;
            if (r >= HALO) r += TILE_H;            // rows 74..83
            int gr = r0b + r;
            int gc = c0 + c;
            float v = 0.f;
            if ((unsigned)gr < (unsigned)H && (unsigned)gc < (unsigned)H)
                v = rb[gr * H + gc];
            xs0[r * PITCH + c] = v;
        }
        // side columns: rows [HALO, HALO+TILE_H), cols [0,HALO) and [HALO+TILE_W, EXW)
        for (int i = tid; i < TILE_H * 2 * HALO; i += NTHREADS) {
            int rr2 = i / (2 * HALO);
            int cc  = i - rr2 * (2 * HALO);
            int r = HALO + rr2;
            int c = (cc < HALO) ? cc : cc + TILE_W;
            int gr = r0b + r;
            int gc = c0 + c;
            float v = 0.f;
            if ((unsigned)gr < (unsigned)H && (unsigned)gc < (unsigned)H)
                v = rb[gr * H + gc];
            xs0[r * PITCH + c] = v;
        }
        __syncthreads();

        // ---- reload center registers from refreshed xs0 ----
        #pragma unroll
        for (int i = 0; i < 4; i++) {
            ulonglong2 v = *(const ulonglong2*)(xs0 + o0 + i * PITCH);
            c01[i] = v.x;
            c23[i] = v.y;
        }
        __syncthreads();
    }
}

extern "C" void kernel_launch(void* const* d_in, const int* in_sizes, int n_in,
                              void* d_out, int out_size) {
    (void)in_sizes; (void)n_in; (void)out_size;
    const float* X  = (const float*)d_in[0];
    const float* Y  = (const float*)d_in[1];
    const float* M1 = (const float*)d_in[2];   // Mask1: [1,1,1024,1024]
    float* out = (float*)d_out;

    cudaFuncSetAttribute(jacobi_persist, cudaFuncAttributeMaxDynamicSharedMemorySize,
                         SMEM_BYTES);

    dim3 grid(GRID_X, GRID_Y);   // (8, 16) = 128 CTAs, single wave on 148 SMs
    jacobi_persist<<<grid, NTHREADS, SMEM_BYTES>>>(X, Y, M1, out);
}

// round 8
// speedup vs baseline: 2.3838x; 1.0814x over previous
#include <cuda_runtime.h>
#include <math.h>

// Reference reduces to: x0 = exp(-50*((X-.5)^2+(Y-.5)^2)); 100x { x = 0.25*Mask1*(N+S+E+W) }
// (down-sweep / coarse solve / up-sweep are dead code w.r.t. the returned value)
//
// Persistent kernel: 128 CTAs (1/SM, single wave), 10 super-steps x 10 smem-resident
// steps; halo exchange via ping-pong global buffers + epoch grid barrier.
// Warps 25..31 (no stacks) skip the compute body via matching-barrier skeleton.

#define H 1024
#define NT 100
#define TSTEPS 10
#define NSS (NT / TSTEPS)               // 10 super-steps
#define TILE_W 128
#define TILE_H 64
#define HALO TSTEPS                     // 10
#define EXW (TILE_W + 2 * HALO)         // 148
#define EXH (TILE_H + 2 * HALO)         // 84
#define PITCH 148
#define GPR 37
#define NBANDS (EXH / 4)                // 21
#define NSTACKS (NBANDS * GPR)          // 777
#define NTHREADS 1024
#define ACT_WARPS ((NSTACKS + 31) / 32) // 25
#define GRID_X (H / TILE_W)             // 8
#define GRID_Y (H / TILE_H)             // 16
#define NCTA (GRID_X * GRID_Y)          // 128
#define SMEM_FLOATS (EXH * PITCH)       // 12432
#define SMEM_BYTES (2 * SMEM_FLOATS * 4)  // 99456 B -> 1 CTA/SM

typedef unsigned long long u64;

__device__ float g_buf0[H * H];
__device__ float g_buf1[H * H];
__device__ volatile unsigned g_arr[NCTA];   // zero-init; epochs, monotone across replays
__device__ volatile unsigned g_go;

__device__ __forceinline__ u64 addx2(u64 a, u64 b) {
    u64 r; asm("add.rn.f32x2 %0,%1,%2;" : "=l"(r) : "l"(a), "l"(b)); return r;
}
__device__ __forceinline__ u64 mulx2(u64 a, u64 b) {
    u64 r; asm("mul.rn.f32x2 %0,%1,%2;" : "=l"(r) : "l"(a), "l"(b)); return r;
}
__device__ __forceinline__ u64 pk(float lo, float hi) {
    u64 r; asm("mov.b64 %0,{%1,%2};" : "=l"(r) : "f"(lo), "f"(hi)); return r;
}
__device__ __forceinline__ void unpk(u64 a, float& lo, float& hi) {
    asm("mov.b64 {%0,%1},%2;" : "=f"(lo), "=f"(hi) : "l"(a));
}

// Epoch grid barrier. All 128 CTAs co-resident (1 CTA/SM, grid < SM count).
__device__ __forceinline__ void grid_barrier(int bid, unsigned ep) {
    __syncthreads();
    if (threadIdx.x == 0) {
        __threadfence();
        g_arr[bid] = ep;
    }
    if (bid == 0) {
        if (threadIdx.x < NCTA) {
            while (g_arr[threadIdx.x] < ep) __nanosleep(32);
        }
        __syncthreads();
        if (threadIdx.x == 0) { __threadfence(); g_go = ep; }
    }
    if (threadIdx.x == 0) {
        while (g_go < ep) __nanosleep(32);
        __threadfence();
    }
    __syncthreads();
}

__global__ void __launch_bounds__(NTHREADS, 1)
jacobi_persist(const float* __restrict__ X, const float* __restrict__ Y,
               const float* __restrict__ mask, float* __restrict__ out) {
    extern __shared__ float smem[];
    float* xs0 = smem;
    float* xs1 = smem + SMEM_FLOATS;

    const int bx = blockIdx.x, by = blockIdx.y;
    const int bid = by * GRID_X + bx;
    const int r0b = by * TILE_H - HALO;
    const int c0  = bx * TILE_W - HALO;
    const int tid = threadIdx.x;
    const int lane = tid & 31;
    const int wid = tid >> 5;

    const unsigned ep0 = g_arr[0];   // equal across CTAs at launch start

    // Initial fill: x0 = exp(-50*((X-.5)^2+(Y-.5)^2)), zero outside domain.
    for (int i = tid; i < SMEM_FLOATS; i += NTHREADS) {
        int r = i / PITCH;
        int c = i - r * PITCH;
        int gr = r0b + r;
        int gc = c0 + c;
        float v = 0.f;
        if ((unsigned)gr < (unsigned)H && (unsigned)gc < (unsigned)H) {
            int g = gr * H + gc;
            float dx = X[g] - 0.5f;
            float dy = Y[g] - 0.5f;
            v = expf(-50.0f * (dx * dx + dy * dy));
        }
        xs0[i] = v;
    }

    const bool act = tid < NSTACKS;
    int band = tid / GPR;
    int cg   = tid - band * GPR;
    if (!act) { band = NBANDS - 1; cg = GPR - 1; }   // clamp: valid addrs, no stores
    const int r0 = band * 4;
    const int o0 = r0 * PITCH + 4 * cg;
    const bool has_up = (band > 0);
    const bool has_dn = (band < NBANDS - 1);

    // Premultiplied mask into packed registers (bounds-checked, zero outside).
    u64 m01[4], m23[4];
    #pragma unroll
    for (int i = 0; i < 4; i++) {
        float a = 0.f, b = 0.f, c = 0.f, d = 0.f;
        int gr = r0b + r0 + i;
        if (act && (unsigned)gr < (unsigned)H) {
            const float* mrow = mask + gr * H;
            int gc = c0 + 4 * cg;
            if ((unsigned)gc       < (unsigned)H) a = 0.25f * mrow[gc];
            if ((unsigned)(gc + 1) < (unsigned)H) b = 0.25f * mrow[gc + 1];
            if ((unsigned)(gc + 2) < (unsigned)H) c = 0.25f * mrow[gc + 2];
            if ((unsigned)(gc + 3) < (unsigned)H) d = 0.25f * mrow[gc + 3];
        }
        m01[i] = pk(a, b);
        m23[i] = pk(c, d);
    }
    __syncthreads();

    // Center values into packed registers.
    u64 c01[4], c23[4];
    #pragma unroll
    for (int i = 0; i < 4; i++) {
        ulonglong2 v = *(const ulonglong2*)(xs0 + o0 + i * PITCH);
        c01[i] = v.x;
        c23[i] = v.y;
    }

    #pragma unroll 1
    for (int ss = 0; ss < NSS; ss++) {
        // ---- 10 smem-resident steps (ends with cur==xs0). Idle warps run a
        //      matching-barrier skeleton (arrive-count semantics, phases align).
        if (wid < ACT_WARPS) {
            float* cur = xs0;
            float* nxt = xs1;
            #pragma unroll
            for (int s = 1; s <= TSTEPS; s++) {
                bool rc[4];
                #pragma unroll
                for (int i = 0; i < 4; i++) {
                    int r = r0 + i;
                    rc[i] = act && (r >= s) && (r < EXH - s);
                }
                // Band-edge (loop-invariant) predication; out-of-cone loads are
                // harmless (results discarded by rc-predicated stores/updates).
                ulonglong2 uu = has_up ? *(const ulonglong2*)(cur + o0 - PITCH)
                                       : make_ulonglong2(0ull, 0ull);
                ulonglong2 dd = has_dn ? *(const ulonglong2*)(cur + o0 + 4 * PITCH)
                                       : make_ulonglong2(0ull, 0ull);

                u64 b01 = uu.x, b23 = uu.y;
                #pragma unroll
                for (int i = 0; i < 4; i++) {
                    float cx, cy, cz, cw;
                    unpk(c01[i], cx, cy);
                    unpk(c23[i], cz, cw);
                    float l  = __shfl_up_sync(0xffffffffu, cw, 1);
                    float rr = __shfl_down_sync(0xffffffffu, cx, 1);
                    int oi = o0 + i * PITCH;
                    if (lane == 0  && rc[i]) l  = cur[oi - 1];
                    if (lane == 31 && rc[i]) rr = cur[oi + 4];
                    u64 dn01, dn23;
                    if (i == 3) { dn01 = dd.x; dn23 = dd.y; }
                    else        { dn01 = c01[i + 1]; dn23 = c23[i + 1]; }
                    u64 mid = pk(cy, cz);
                    u64 h01 = addx2(pk(l, cx), mid);
                    u64 h23 = addx2(mid, pk(cw, rr));
                    u64 v01 = mulx2(addx2(addx2(b01, dn01), h01), m01[i]);
                    u64 v23 = mulx2(addx2(addx2(b23, dn23), h23), m23[i]);
                    b01 = c01[i];
                    b23 = c23[i];
                    if (rc[i]) {
                        c01[i] = v01;
                        c23[i] = v23;
                        *(ulonglong2*)(nxt + oi) = make_ulonglong2(v01, v23);
                    }
                }
                float* t = cur; cur = nxt; nxt = t;
                __syncthreads();
            }
        } else {
            #pragma unroll
            for (int s = 1; s <= TSTEPS; s++) __syncthreads();
        }

        // ---- write interior (rows/cols [HALO, HALO+TILE)) from xs0 ----
        float* wb = (ss == NSS - 1) ? out : ((ss & 1) ? g_buf1 : g_buf0);
        #pragma unroll
        for (int k = 0; k < (TILE_H * TILE_W) / NTHREADS; k++) {   // 8 iterations
            int idx = tid + k * NTHREADS;
            int r = HALO + (idx >> 7);
            int c = HALO + (idx & 127);
            wb[(r0b + r) * H + (c0 + c)] = xs0[r * PITCH + c];
        }
        if (ss == NSS - 1) break;

        grid_barrier(bid, ep0 + (unsigned)ss + 1u);

        // ---- refresh halo ring of xs0 from this super-step's buffer ----
        const float* rb = (ss & 1) ? g_buf1 : g_buf0;
        for (int i = tid; i < 2 * HALO * EXW; i += NTHREADS) {
            int r = i / EXW;
            int c = i - r * EXW;
            if (r >= HALO) r += TILE_H;
            int gr = r0b + r;
            int gc = c0 + c;
            float v = 0.f;
            if ((unsigned)gr < (unsigned)H && (unsigned)gc < (unsigned)H)
                v = rb[gr * H + gc];
            xs0[r * PITCH + c] = v;
        }
        for (int i = tid; i < TILE_H * 2 * HALO; i += NTHREADS) {
            int rr2 = i / (2 * HALO);
            int cc  = i - rr2 * (2 * HALO);
            int r = HALO + rr2;
            int c = (cc < HALO) ? cc : cc + TILE_W;
            int gr = r0b + r;
            int gc = c0 + c;
            float v = 0.f;
            if ((unsigned)gr < (unsigned)H && (unsigned)gc < (unsigned)H)
                v = rb[gr * H + gc];
            xs0[r * PITCH + c] = v;
        }
        __syncthreads();

        // ---- reload center registers from refreshed xs0 ----
        #pragma unroll
        for (int i = 0; i < 4; i++) {
            ulonglong2 v = *(const ulonglong2*)(xs0 + o0 + i * PITCH);
            c01[i] = v.x;
            c23[i] = v.y;
        }
        __syncthreads();
    }
}

extern "C" void kernel_launch(void* const* d_in, const int* in_sizes, int n_in,
                              void* d_out, int out_size) {
    (void)in_sizes; (void)n_in; (void)out_size;
    const float* X  = (const float*)d_in[0];
    const float* Y  = (const float*)d_in[1];
    const float* M1 = (const float*)d_in[2];   // Mask1: [1,1,1024,1024]
    float* out = (float*)d_out;

    cudaFuncSetAttribute(jacobi_persist, cudaFuncAttributeMaxDynamicSharedMemorySize,
                         SMEM_BYTES);

    dim3 grid(GRID_X, GRID_Y);   // (8, 16) = 128 CTAs, single wave on 148 SMs
    jacobi_persist<<<grid, NTHREADS, SMEM_BYTES>>>(X, Y, M1, out);
}